// round 4
// baseline (speedup 1.0000x reference)
#include <cuda_runtime.h>

#define BB 16
#define SS 2048
#define FF 64
#define RR (BB*SS)
#define CH 64
#define CHM (SS/CH)   // 32

// ---- scratch (device globals; no allocations allowed) ----
__device__ __align__(128) float g_ts[SS];       // sorted template
__device__ __align__(128) int   g_perm[SS];     // sort permutation (sorted -> original)
__device__ __align__(128) float g_us[SS];       // exp(t) sorted order
__device__ __align__(128) float g_vs[SS];       // exp(-t) sorted order
__device__ __align__(128) float g_uo[SS];       // exp(t) original order
__device__ __align__(128) float g_vo[SS];       // exp(-t) original order
__device__ __align__(128) float g_P[SS+1];      // exclusive prefix of exp(ts)
__device__ __align__(128) float g_Q[SS+1];      // inclusive suffix of exp(-ts)
__device__ __align__(128) float g_pu[BB*CH*FF]; // per-chunk sum of u*f
__device__ __align__(128) float g_pv[BB*CH*FF]; // per-chunk sum of v*f
__device__ __align__(128) float g_PU[BB*CH*FF]; // exclusive prefix over chunks of pu
__device__ __align__(128) float g_QV[BB*CH*FF]; // exclusive suffix over chunks of pv

// KA: rank sort (O(N^2), warp per element) + all exps.
__global__ void ka_rank(const float* __restrict__ tmpl) {
    __shared__ float sh[SS];
    int tid = threadIdx.x;
    for (int i = tid; i < SS; i += 256) sh[i] = tmpl[i];
    __syncthreads();
    int e = blockIdx.x * 8 + (tid >> 5);
    int lane = tid & 31;
    float t = sh[e];
    int cnt = 0;
    #pragma unroll 8
    for (int j = lane; j < SS; j += 32) {
        float tj = sh[j];
        cnt += (tj < t) || (tj == t && j < e);
    }
    #pragma unroll
    for (int o = 16; o; o >>= 1) cnt += __shfl_down_sync(0xffffffffu, cnt, o);
    if (lane == 0) {
        float u = __expf(t), v = __expf(-t);
        g_ts[cnt] = t; g_perm[cnt] = e;
        g_us[cnt] = u; g_vs[cnt] = v;
        g_uo[e]  = u; g_vo[e]  = v;
    }
}

// KB: P/Q scans over sorted exps (1 block, 1024 threads, Hillis-Steele)
__global__ void kb_scan() {
    __shared__ float c[1024];
    int tid = threadIdx.x;
    {
        float e0 = g_us[2*tid], e1 = g_us[2*tid+1];
        float cc = e0 + e1;
        c[tid] = cc; __syncthreads();
        for (int off = 1; off < 1024; off <<= 1) {
            float tv = c[tid];
            if (tid >= off) tv += c[tid - off];
            __syncthreads(); c[tid] = tv; __syncthreads();
        }
        float incl = c[tid];
        float excl = incl - cc;
        g_P[2*tid]   = excl;
        g_P[2*tid+1] = excl + e0;
        if (tid == 1023) g_P[SS] = incl;
        __syncthreads();
    }
    {
        float d0 = g_vs[SS-1-2*tid];
        float d1 = g_vs[SS-2-2*tid];
        float cc = d0 + d1;
        c[tid] = cc; __syncthreads();
        for (int off = 1; off < 1024; off <<= 1) {
            float tv = c[tid];
            if (tid >= off) tv += c[tid - off];
            __syncthreads(); c[tid] = tv; __syncthreads();
        }
        float incl = c[tid];
        float excl = incl - cc;
        g_Q[SS - 2*tid]     = excl;
        g_Q[SS - (2*tid+1)] = excl + d0;
        if (tid == 1023) g_Q[0] = incl;
    }
}

// KD: per-chunk partial sums of u*f and v*f. One (b,chunk) per block.
// block 256 = 4 m-slices x 64 f; grid (16, 64)
__global__ void kd_part(const float* __restrict__ feat) {
    __shared__ float rsu[4][FF];
    __shared__ float rsv[4][FF];
    int tid = threadIdx.x;
    int f  = tid & 63;
    int sl = tid >> 6;
    int b  = blockIdx.x, ch = blockIdx.y;
    int m0 = ch * CHM + sl * (CHM/4);
    const float* fb = feat + (size_t)b * SS * FF;
    float su = 0.f, sv = 0.f;
    #pragma unroll
    for (int m = m0; m < m0 + CHM/4; ++m) {
        float x = fb[(size_t)g_perm[m] * FF + f];
        su += g_us[m] * x;
        sv += g_vs[m] * x;
    }
    rsu[sl][f] = su; rsv[sl][f] = sv;
    __syncthreads();
    if (sl == 0) {
        su = rsu[0][f] + rsu[1][f] + rsu[2][f] + rsu[3][f];
        sv = rsv[0][f] + rsv[1][f] + rsv[2][f] + rsv[3][f];
        g_pu[(b*CH + ch)*FF + f] = su;
        g_pv[(b*CH + ch)*FF + f] = sv;
    }
}

// KC: exclusive chunk-prefix (PU) and exclusive chunk-suffix (QV).
// grid BB, block FF
__global__ void kc_scan() {
    int b = blockIdx.x, f = threadIdx.x;
    float acc = 0.f;
    #pragma unroll
    for (int c = 0; c < CH; ++c) {
        g_PU[(b*CH + c)*FF + f] = acc;
        acc += g_pu[(b*CH + c)*FF + f];
    }
    float accv = 0.f;
    #pragma unroll
    for (int c = CH - 1; c >= 0; --c) {
        g_QV[(b*CH + c)*FF + f] = accv;
        accv += g_pv[(b*CH + c)*FF + f];
    }
}

// per-row coefficients helper
__device__ __forceinline__ void row_coeffs(float s, float& A, float& Bv, int& k) {
    int lo = 0, hi = SS;
    while (lo < hi) {
        int mid = (lo + hi) >> 1;
        if (g_ts[mid] <= s) lo = mid + 1; else hi = mid;
    }
    k = lo;
    float e  = __expf(-s);
    float ei = __expf(s);
    float inv = 1.0f / (e * g_P[k] + ei * g_Q[k]);
    A  = e * inv;
    Bv = ei * inv;
}

// KMAIN: warp per row. Fused: aligned (chunk prefix + within-chunk remainder,
// feat reads hit L2) + path (smem-staged u/v, streaming float4 stores).
// grid RR/8, block 256
__global__ void __launch_bounds__(256) kmain(const float* __restrict__ score,
                                             const float* __restrict__ feat,
                                             float* __restrict__ out) {
    __shared__ float4 su4[SS/4];   // 8 KB
    __shared__ float4 sv4[SS/4];   // 8 KB
    int tid = threadIdx.x;
    for (int i = tid; i < SS/4; i += 256) {
        su4[i] = reinterpret_cast<const float4*>(g_uo)[i];
        sv4[i] = reinterpret_cast<const float4*>(g_vo)[i];
    }
    __syncthreads();
    int warp = tid >> 5, lane = tid & 31;
    int r = blockIdx.x * 8 + warp;
    float A, Bv; int k;
    row_coeffs(score[r], A, Bv, k);
    int b = r >> 11;

    // ---- aligned row ----
    int c0 = (k >= SS ? SS - 1 : k) >> 5;   // chunk containing the split
    int m0 = c0 * CHM;
    const float* fb = feat + (size_t)b * SS * FF;
    float aU0 = 0.f, aU1 = 0.f, aV0 = 0.f, aV1 = 0.f;
    #pragma unroll 8
    for (int m = m0; m < m0 + CHM; ++m) {
        int p = g_perm[m];
        float um = g_us[m], vm = g_vs[m];
        const float* xr = fb + (size_t)p * FF;
        float x0 = xr[lane], x1 = xr[lane + 32];
        if (m < k) { aU0 += um * x0; aU1 += um * x1; }
        else       { aV0 += vm * x0; aV1 += vm * x1; }
    }
    int base = (b*CH + c0)*FF;
    float o0 = A * (g_PU[base + lane]      + aU0) + Bv * (g_QV[base + lane]      + aV0);
    float o1 = A * (g_PU[base + lane + 32] + aU1) + Bv * (g_QV[base + lane + 32] + aV1);
    out[(size_t)r * FF + lane]      = o0;
    out[(size_t)r * FF + lane + 32] = o1;

    // ---- path row ----
    float4* prow4 = reinterpret_cast<float4*>(out + (size_t)RR * FF + (size_t)r * SS);
    #pragma unroll 4
    for (int j4 = lane; j4 < SS/4; j4 += 32) {
        float4 u = su4[j4], v = sv4[j4];
        float4 p;
        p.x = fminf(A*u.x, Bv*v.x);
        p.y = fminf(A*u.y, Bv*v.y);
        p.z = fminf(A*u.z, Bv*v.z);
        p.w = fminf(A*u.w, Bv*v.w);
        __stcs(prow4 + j4, p);
    }
}

extern "C" void kernel_launch(void* const* d_in, const int* in_sizes, int n_in,
                              void* d_out, int out_size) {
    const float* score = (const float*)d_in[0];   // [16,2048,1]
    const float* feat  = (const float*)d_in[1];   // [16,2048,64]
    const float* tmpl  = (const float*)d_in[2];   // [1,2048,1]
    float* out = (float*)d_out;                   // aligned [16,2048,64] then path [16,2048,2048]

    ka_rank<<<SS/8, 256>>>(tmpl);
    kb_scan<<<1, 1024>>>();
    kd_part<<<dim3(BB, CH), 256>>>(feat);
    kc_scan<<<BB, FF>>>();
    kmain<<<RR/8, 256>>>(score, feat, out);
}

// round 5
// speedup vs baseline: 1.2444x; 1.2444x over previous
#include <cuda_runtime.h>

#define BB 16
#define SS 2048
#define FF 64
#define RR (BB*SS)
#define CH 64
#define CHM (SS/CH)   // 32

// ---- scratch (device globals; no allocations allowed) ----
__device__ __align__(128) float g_ts[SS];       // sorted template
__device__ __align__(128) int   g_perm[SS];     // sort permutation (sorted -> original)
__device__ __align__(128) float g_us[SS];       // exp(t) sorted order
__device__ __align__(128) float g_vs[SS];       // exp(-t) sorted order
__device__ __align__(128) float g_uo[SS];       // exp(t) original order
__device__ __align__(128) float g_vo[SS];       // exp(-t) original order
__device__ __align__(128) float g_P[SS+1];      // exclusive prefix of exp(ts)
__device__ __align__(128) float g_Q[SS+1];      // inclusive suffix of exp(-ts)
__device__ __align__(128) float g_pu[BB*CH*FF]; // per-chunk sum of u*f
__device__ __align__(128) float g_pv[BB*CH*FF]; // per-chunk sum of v*f
__device__ __align__(128) float g_PU[BB*CH*FF]; // exclusive prefix over chunks of pu
__device__ __align__(128) float g_QV[BB*CH*FF]; // exclusive suffix over chunks of pv

// KA: rank sort (O(N^2), warp per element) + all exps.
__global__ void ka_rank(const float* __restrict__ tmpl) {
    __shared__ float sh[SS];
    int tid = threadIdx.x;
    for (int i = tid; i < SS; i += 256) sh[i] = tmpl[i];
    __syncthreads();
    int e = blockIdx.x * 8 + (tid >> 5);
    int lane = tid & 31;
    float t = sh[e];
    int cnt = 0;
    #pragma unroll 8
    for (int j = lane; j < SS; j += 32) {
        float tj = sh[j];
        cnt += (tj < t) || (tj == t && j < e);
    }
    #pragma unroll
    for (int o = 16; o; o >>= 1) cnt += __shfl_down_sync(0xffffffffu, cnt, o);
    if (lane == 0) {
        float u = __expf(t), v = __expf(-t);
        g_ts[cnt] = t; g_perm[cnt] = e;
        g_us[cnt] = u; g_vs[cnt] = v;
        g_uo[e]  = u; g_vo[e]  = v;
    }
}

// KB: P/Q scans over sorted exps (1 block, 1024 threads, Hillis-Steele)
__global__ void kb_scan() {
    __shared__ float c[1024];
    int tid = threadIdx.x;
    {
        float e0 = g_us[2*tid], e1 = g_us[2*tid+1];
        float cc = e0 + e1;
        c[tid] = cc; __syncthreads();
        for (int off = 1; off < 1024; off <<= 1) {
            float tv = c[tid];
            if (tid >= off) tv += c[tid - off];
            __syncthreads(); c[tid] = tv; __syncthreads();
        }
        float incl = c[tid];
        float excl = incl - cc;
        g_P[2*tid]   = excl;
        g_P[2*tid+1] = excl + e0;
        if (tid == 1023) g_P[SS] = incl;
        __syncthreads();
    }
    {
        float d0 = g_vs[SS-1-2*tid];
        float d1 = g_vs[SS-2-2*tid];
        float cc = d0 + d1;
        c[tid] = cc; __syncthreads();
        for (int off = 1; off < 1024; off <<= 1) {
            float tv = c[tid];
            if (tid >= off) tv += c[tid - off];
            __syncthreads(); c[tid] = tv; __syncthreads();
        }
        float incl = c[tid];
        float excl = incl - cc;
        g_Q[SS - 2*tid]     = excl;
        g_Q[SS - (2*tid+1)] = excl + d0;
        if (tid == 1023) g_Q[0] = incl;
    }
}

// KD: per-chunk partial sums of u*f and v*f. One (b,chunk) per block.
// block 256 = 4 m-slices x 64 f; grid (16, 64)
__global__ void kd_part(const float* __restrict__ feat) {
    __shared__ float rsu[4][FF];
    __shared__ float rsv[4][FF];
    int tid = threadIdx.x;
    int f  = tid & 63;
    int sl = tid >> 6;
    int b  = blockIdx.x, ch = blockIdx.y;
    int m0 = ch * CHM + sl * (CHM/4);
    const float* fb = feat + (size_t)b * SS * FF;
    float su = 0.f, sv = 0.f;
    #pragma unroll
    for (int m = m0; m < m0 + CHM/4; ++m) {
        float x = fb[(size_t)g_perm[m] * FF + f];
        su += g_us[m] * x;
        sv += g_vs[m] * x;
    }
    rsu[sl][f] = su; rsv[sl][f] = sv;
    __syncthreads();
    if (sl == 0) {
        su = rsu[0][f] + rsu[1][f] + rsu[2][f] + rsu[3][f];
        sv = rsv[0][f] + rsv[1][f] + rsv[2][f] + rsv[3][f];
        g_pu[(b*CH + ch)*FF + f] = su;
        g_pv[(b*CH + ch)*FF + f] = sv;
    }
}

// KC: exclusive chunk-prefix (PU) and exclusive chunk-suffix (QV).
// One block per batch: stage 64x64 partials in smem (coalesced), scan columns
// in parallel (128 threads: 64 prefix + 64 suffix), store coalesced.
// grid BB, block 256
__global__ void kc_scan() {
    __shared__ float spu[CH*FF];   // 16 KB
    __shared__ float spv[CH*FF];   // 16 KB
    int b = blockIdx.x, tid = threadIdx.x;
    const float* pu = g_pu + b*CH*FF;
    const float* pv = g_pv + b*CH*FF;
    for (int i = tid; i < CH*FF; i += 256) {
        spu[i] = pu[i];
        spv[i] = pv[i];
    }
    __syncthreads();
    if (tid < 64) {                 // exclusive prefix over chunks, column f=tid
        int f = tid; float acc = 0.f;
        #pragma unroll
        for (int c = 0; c < CH; ++c) {
            float t = spu[c*FF + f];
            spu[c*FF + f] = acc;
            acc += t;
        }
    } else if (tid < 128) {         // exclusive suffix over chunks, column f=tid-64
        int f = tid - 64; float acc = 0.f;
        #pragma unroll
        for (int c = CH - 1; c >= 0; --c) {
            float t = spv[c*FF + f];
            spv[c*FF + f] = acc;
            acc += t;
        }
    }
    __syncthreads();
    float* PU = g_PU + b*CH*FF;
    float* QV = g_QV + b*CH*FF;
    for (int i = tid; i < CH*FF; i += 256) {
        PU[i] = spu[i];
        QV[i] = spv[i];
    }
}

// per-row coefficients helper
__device__ __forceinline__ void row_coeffs(float s, float& A, float& Bv, int& k) {
    int lo = 0, hi = SS;
    while (lo < hi) {
        int mid = (lo + hi) >> 1;
        if (g_ts[mid] <= s) lo = mid + 1; else hi = mid;
    }
    k = lo;
    float e  = __expf(-s);
    float ei = __expf(s);
    float inv = 1.0f / (e * g_P[k] + ei * g_Q[k]);
    A  = e * inv;
    Bv = ei * inv;
}

// KMAIN: warp per row. Fused: aligned (chunk prefix + within-chunk remainder,
// feat reads hit L2) + path (smem-staged u/v, streaming float4 stores).
// grid RR/8, block 256
__global__ void __launch_bounds__(256) kmain(const float* __restrict__ score,
                                             const float* __restrict__ feat,
                                             float* __restrict__ out) {
    __shared__ float4 su4[SS/4];   // 8 KB
    __shared__ float4 sv4[SS/4];   // 8 KB
    int tid = threadIdx.x;
    for (int i = tid; i < SS/4; i += 256) {
        su4[i] = reinterpret_cast<const float4*>(g_uo)[i];
        sv4[i] = reinterpret_cast<const float4*>(g_vo)[i];
    }
    __syncthreads();
    int warp = tid >> 5, lane = tid & 31;
    int r = blockIdx.x * 8 + warp;
    float A, Bv; int k;
    row_coeffs(score[r], A, Bv, k);
    int b = r >> 11;

    // ---- aligned row ----
    int c0 = (k >= SS ? SS - 1 : k) >> 5;   // chunk containing the split
    int m0 = c0 * CHM;
    const float* fb = feat + (size_t)b * SS * FF;
    float aU0 = 0.f, aU1 = 0.f, aV0 = 0.f, aV1 = 0.f;
    #pragma unroll 8
    for (int m = m0; m < m0 + CHM; ++m) {
        int p = g_perm[m];
        float um = g_us[m], vm = g_vs[m];
        const float* xr = fb + (size_t)p * FF;
        float x0 = xr[lane], x1 = xr[lane + 32];
        if (m < k) { aU0 += um * x0; aU1 += um * x1; }
        else       { aV0 += vm * x0; aV1 += vm * x1; }
    }
    int base = (b*CH + c0)*FF;
    float o0 = A * (g_PU[base + lane]      + aU0) + Bv * (g_QV[base + lane]      + aV0);
    float o1 = A * (g_PU[base + lane + 32] + aU1) + Bv * (g_QV[base + lane + 32] + aV1);
    out[(size_t)r * FF + lane]      = o0;
    out[(size_t)r * FF + lane + 32] = o1;

    // ---- path row ----
    float4* prow4 = reinterpret_cast<float4*>(out + (size_t)RR * FF + (size_t)r * SS);
    #pragma unroll 4
    for (int j4 = lane; j4 < SS/4; j4 += 32) {
        float4 u = su4[j4], v = sv4[j4];
        float4 p;
        p.x = fminf(A*u.x, Bv*v.x);
        p.y = fminf(A*u.y, Bv*v.y);
        p.z = fminf(A*u.z, Bv*v.z);
        p.w = fminf(A*u.w, Bv*v.w);
        __stcs(prow4 + j4, p);
    }
}

extern "C" void kernel_launch(void* const* d_in, const int* in_sizes, int n_in,
                              void* d_out, int out_size) {
    const float* score = (const float*)d_in[0];   // [16,2048,1]
    const float* feat  = (const float*)d_in[1];   // [16,2048,64]
    const float* tmpl  = (const float*)d_in[2];   // [1,2048,1]
    float* out = (float*)d_out;                   // aligned [16,2048,64] then path [16,2048,2048]

    ka_rank<<<SS/8, 256>>>(tmpl);
    kb_scan<<<1, 1024>>>();
    kd_part<<<dim3(BB, CH), 256>>>(feat);
    kc_scan<<<BB, 256>>>();
    kmain<<<RR/8, 256>>>(score, feat, out);
}

// round 6
// speedup vs baseline: 1.4411x; 1.1580x over previous
#include <cuda_runtime.h>

#define BB 16
#define SS 2048
#define FF 64
#define RR (BB*SS)
#define SC 256          // sub-chunks per batch
#define SCM 8           // m per sub-chunk

// ---- scratch (device globals; no allocations allowed) ----
__device__ __align__(128) float g_ts[SS];       // sorted template
__device__ __align__(128) int   g_perm[SS];     // sort permutation (sorted -> original)
__device__ __align__(128) float g_us[SS];       // exp(t) sorted order
__device__ __align__(128) float g_vs[SS];       // exp(-t) sorted order
__device__ __align__(128) float g_P[SS+1];      // exclusive prefix of exp(ts)
__device__ __align__(128) float g_Q[SS+1];      // inclusive suffix of exp(-ts)
__device__ __align__(128) float g_PU8[BB*SC*FF]; // exclusive sub-chunk prefix of u*f
__device__ __align__(128) float g_QV8[BB*SC*FF]; // exclusive sub-chunk suffix of v*f

// KA: rank sort (O(N^2), warp per element) + sorted exps.
__global__ void ka_rank(const float* __restrict__ tmpl) {
    __shared__ float sh[SS];
    int tid = threadIdx.x;
    for (int i = tid; i < SS; i += 256) sh[i] = tmpl[i];
    __syncthreads();
    int e = blockIdx.x * 8 + (tid >> 5);
    int lane = tid & 31;
    float t = sh[e];
    int cnt = 0;
    #pragma unroll 8
    for (int j = lane; j < SS; j += 32) {
        float tj = sh[j];
        cnt += (tj < t) || (tj == t && j < e);
    }
    #pragma unroll
    for (int o = 16; o; o >>= 1) cnt += __shfl_down_sync(0xffffffffu, cnt, o);
    if (lane == 0) {
        g_ts[cnt] = t; g_perm[cnt] = e;
        g_us[cnt] = __expf(t); g_vs[cnt] = __expf(-t);
    }
}

// KB: P/Q scans over sorted exps (1 block, 1024 threads, Hillis-Steele)
__global__ void kb_scan() {
    __shared__ float c[1024];
    int tid = threadIdx.x;
    {
        float e0 = g_us[2*tid], e1 = g_us[2*tid+1];
        float cc = e0 + e1;
        c[tid] = cc; __syncthreads();
        for (int off = 1; off < 1024; off <<= 1) {
            float tv = c[tid];
            if (tid >= off) tv += c[tid - off];
            __syncthreads(); c[tid] = tv; __syncthreads();
        }
        float incl = c[tid];
        float excl = incl - cc;
        g_P[2*tid]   = excl;
        g_P[2*tid+1] = excl + e0;
        if (tid == 1023) g_P[SS] = incl;
        __syncthreads();
    }
    {
        float d0 = g_vs[SS-1-2*tid];
        float d1 = g_vs[SS-2-2*tid];
        float cc = d0 + d1;
        c[tid] = cc; __syncthreads();
        for (int off = 1; off < 1024; off <<= 1) {
            float tv = c[tid];
            if (tid >= off) tv += c[tid - off];
            __syncthreads(); c[tid] = tv; __syncthreads();
        }
        float incl = c[tid];
        float excl = incl - cc;
        g_Q[SS - 2*tid]     = excl;
        g_Q[SS - (2*tid+1)] = excl + d0;
        if (tid == 1023) g_Q[0] = incl;
    }
}

// K2: per-batch sub-chunk(8) partials + exclusive prefix/suffix tables.
// grid 16 (one block per batch), block 1024 = 16 slices x 64 f.
// Each thread owns 128 m (16 sub-chunks) kept in registers; cross-slice scan in smem.
__global__ void __launch_bounds__(1024) k2_part8(const float* __restrict__ feat) {
    __shared__ float s128u[16][FF];   // 4 KB
    __shared__ float s128v[16][FF];   // 4 KB
    int tid = threadIdx.x;
    int f  = tid & 63;
    int sl = tid >> 6;                // 0..15
    int b  = blockIdx.x;
    const float* fb = feat + (size_t)b * SS * FF;
    int m0 = sl * 128;
    float r8u[16], r8v[16];
    float tu = 0.f, tv = 0.f;
    #pragma unroll
    for (int i = 0; i < 16; ++i) {
        float au = 0.f, av = 0.f;
        #pragma unroll
        for (int j = 0; j < 8; ++j) {
            int m = m0 + i*8 + j;
            float x = fb[(size_t)g_perm[m] * FF + f];
            au += g_us[m] * x;
            av += g_vs[m] * x;
        }
        r8u[i] = au; r8v[i] = av;
        tu += au; tv += av;
    }
    s128u[sl][f] = tu; s128v[sl][f] = tv;
    __syncthreads();
    float offU = 0.f, offV = 0.f;
    #pragma unroll
    for (int s2 = 0; s2 < 16; ++s2) {
        float pu = s128u[s2][f], pv = s128v[s2][f];
        if (s2 < sl) offU += pu;
        if (s2 > sl) offV += pv;
    }
    float acc = offU;
    #pragma unroll
    for (int i = 0; i < 16; ++i) {
        g_PU8[((size_t)b*SC + sl*16 + i)*FF + f] = acc;
        acc += r8u[i];
    }
    float accv = offV;
    #pragma unroll
    for (int i = 15; i >= 0; --i) {
        g_QV8[((size_t)b*SC + sl*16 + i)*FF + f] = accv;
        accv += r8v[i];
    }
}

// per-row coefficients helper
__device__ __forceinline__ void row_coeffs(float s, float& A, float& Bv, int& k) {
    int lo = 0, hi = SS;
    while (lo < hi) {
        int mid = (lo + hi) >> 1;
        if (g_ts[mid] <= s) lo = mid + 1; else hi = mid;
    }
    k = lo;
    float e  = __expf(-s);
    float ei = __expf(s);
    float inv = 1.0f / (e * g_P[k] + ei * g_Q[k]);
    A  = e * inv;
    Bv = ei * inv;
}

// KMAIN: warp per row, 32 rows/block, grid 1024.
// u/v computed in-block from tmpl (8 KB read). Aligned = PU8/QV8 + <=8-element
// remainder (2 KB L2 reads/row). Path = smem u/v + streaming float4 stores.
__global__ void __launch_bounds__(1024) kmain(const float* __restrict__ score,
                                              const float* __restrict__ feat,
                                              const float* __restrict__ tmpl,
                                              float* __restrict__ out) {
    __shared__ float su[SS];   // 8 KB
    __shared__ float sv[SS];   // 8 KB
    int tid = threadIdx.x;
    for (int i = tid; i < SS; i += 1024) {
        float t = tmpl[i];
        su[i] = __expf(t);
        sv[i] = __expf(-t);
    }
    __syncthreads();
    int w = tid >> 5, lane = tid & 31;
    int r = blockIdx.x * 32 + w;
    float A, Bv; int k;
    row_coeffs(score[r], A, Bv, k);
    int b = r >> 11;

    // ---- aligned row ----
    int c8 = (k >= SS ? SS - 1 : k) >> 3;   // sub-chunk containing the split
    int m0 = c8 * SCM;
    const float* fb = feat + (size_t)b * SS * FF;
    float aU0 = 0.f, aU1 = 0.f, aV0 = 0.f, aV1 = 0.f;
    #pragma unroll
    for (int j = 0; j < SCM; ++j) {
        int m = m0 + j;
        int p = g_perm[m];
        float um = g_us[m], vm = g_vs[m];
        const float* xr = fb + (size_t)p * FF;
        float x0 = xr[lane], x1 = xr[lane + 32];
        if (m < k) { aU0 += um * x0; aU1 += um * x1; }
        else       { aV0 += vm * x0; aV1 += vm * x1; }
    }
    int base = (b*SC + c8)*FF;
    out[(size_t)r * FF + lane]      = A*(g_PU8[base + lane]      + aU0) + Bv*(g_QV8[base + lane]      + aV0);
    out[(size_t)r * FF + lane + 32] = A*(g_PU8[base + lane + 32] + aU1) + Bv*(g_QV8[base + lane + 32] + aV1);

    // ---- path row ----
    const float4* su4 = reinterpret_cast<const float4*>(su);
    const float4* sv4 = reinterpret_cast<const float4*>(sv);
    float4* prow4 = reinterpret_cast<float4*>(out + (size_t)RR * FF + (size_t)r * SS);
    #pragma unroll 4
    for (int j4 = lane; j4 < SS/4; j4 += 32) {
        float4 u = su4[j4], v = sv4[j4];
        float4 p;
        p.x = fminf(A*u.x, Bv*v.x);
        p.y = fminf(A*u.y, Bv*v.y);
        p.z = fminf(A*u.z, Bv*v.z);
        p.w = fminf(A*u.w, Bv*v.w);
        __stcs(prow4 + j4, p);
    }
}

extern "C" void kernel_launch(void* const* d_in, const int* in_sizes, int n_in,
                              void* d_out, int out_size) {
    const float* score = (const float*)d_in[0];   // [16,2048,1]
    const float* feat  = (const float*)d_in[1];   // [16,2048,64]
    const float* tmpl  = (const float*)d_in[2];   // [1,2048,1]
    float* out = (float*)d_out;                   // aligned [16,2048,64] then path [16,2048,2048]

    ka_rank<<<SS/8, 256>>>(tmpl);
    kb_scan<<<1, 1024>>>();
    k2_part8<<<BB, 1024>>>(feat);
    kmain<<<RR/32, 1024>>>(score, feat, tmpl, out);
}